// round 5
// baseline (speedup 1.0000x reference)
#include <cuda_runtime.h>
#include <cstdint>

// AlignedLinear: y[n, o*9+d] = alpha * sum_i x[n, i*9+d] * K[r(d), i, o]
// r(d) = 0 for d=0, 1 for d=1..3, 2 for d=4..8.
// TF32 mma.sync; X tile staged in SMEM, outputs overwrite dead X columns in
// place, single coalesced store at the end. 512 threads (16 warps, 2Mx8N).

#define MT        32            // nodes per CTA
#define DIMT      9
#define MUL       128
#define ROWF      1152          // MUL*DIMT floats per node row
#define XS        1156          // ROWF + 4  (stride-9 A reads conflict-free)
#define KS        136           // MUL + 8   (8 mod 32 -> B reads conflict-free)
#define NTHREADS  512
#define NWARPN    8             // warps along N
#define WN_TILE   16            // output cols per warp (2 n-tiles of 8)
#define ALPHA_F   0.08838834764831845f  // sqrt(1/128)

static __device__ __forceinline__ uint32_t f2tf32(float f) {
    uint32_t u;
    asm("cvt.rna.tf32.f32 %0, %1;" : "=r"(u) : "f"(f));
    return u;
}

static __device__ __forceinline__ void mma_tf32(float c[4],
    uint32_t a0, uint32_t a1, uint32_t a2, uint32_t a3,
    uint32_t b0, uint32_t b1)
{
    asm volatile(
        "mma.sync.aligned.m16n8k8.row.col.f32.tf32.tf32.f32 "
        "{%0,%1,%2,%3}, {%4,%5,%6,%7}, {%8,%9}, {%0,%1,%2,%3};"
        : "+f"(c[0]), "+f"(c[1]), "+f"(c[2]), "+f"(c[3])
        : "r"(a0), "r"(a1), "r"(a2), "r"(a3), "r"(b0), "r"(b1));
}

// One irrep group: stage K_R, GEMM all DC dims of this irrep over k, then
// write alpha*C back into sX (overwriting the now-dead X columns o*9+d).
template<int R, int D0, int DC>
static __device__ __forceinline__ void process_group(
    uint32_t* __restrict__ sX, uint32_t* __restrict__ sK,
    const float* __restrict__ kern,
    int tid, int g, int tg, int wm, int wn)
{
    __syncthreads();   // prior users of sK / sX columns done (also X staging)
    {
        const float4* kg =
            reinterpret_cast<const float4*>(kern + (size_t)R * MUL * MUL);
        #pragma unroll
        for (int it = tid; it < MUL * (MUL / 4); it += NTHREADS) {
            int row = it >> 5;
            int c4  = it & 31;
            float4 v = kg[it];
            uint32_t* dst = sK + row * KS + c4 * 4;
            dst[0] = f2tf32(v.x);
            dst[1] = f2tf32(v.y);
            dst[2] = f2tf32(v.z);
            dst[3] = f2tf32(v.w);
        }
    }
    __syncthreads();

    float c[DC][2][4];
    #pragma unroll
    for (int dd = 0; dd < DC; ++dd)
        #pragma unroll
        for (int nt = 0; nt < 2; ++nt)
            #pragma unroll
            for (int i = 0; i < 4; ++i) c[dd][nt][i] = 0.f;

    #pragma unroll 2
    for (int kk = 0; kk < MUL; kk += 8) {
        // B fragments: shared across all DC dims of this irrep
        uint32_t b[2][2];
        #pragma unroll
        for (int nt = 0; nt < 2; ++nt) {
            int o = wn + nt * 8 + g;
            b[nt][0] = sK[(kk + tg    ) * KS + o];
            b[nt][1] = sK[(kk + tg + 4) * KS + o];
        }
        #pragma unroll
        for (int dd = 0; dd < DC; ++dd) {
            const int d = D0 + dd;
            uint32_t a0 = sX[(wm + g    ) * XS + (kk + tg    ) * DIMT + d];
            uint32_t a1 = sX[(wm + g + 8) * XS + (kk + tg    ) * DIMT + d];
            uint32_t a2 = sX[(wm + g    ) * XS + (kk + tg + 4) * DIMT + d];
            uint32_t a3 = sX[(wm + g + 8) * XS + (kk + tg + 4) * DIMT + d];
            #pragma unroll
            for (int nt = 0; nt < 2; ++nt)
                mma_tf32(c[dd][nt], a0, a1, a2, a3, b[nt][0], b[nt][1]);
        }
    }

    __syncthreads();   // all warps finished reading X columns of this irrep

    // Overwrite the dead X columns with alpha*C (same column indices o*9+d).
    #pragma unroll
    for (int dd = 0; dd < DC; ++dd) {
        const int d = D0 + dd;
        #pragma unroll
        for (int nt = 0; nt < 2; ++nt) {
            int o = wn + nt * 8 + 2 * tg;
            uint32_t* lo = sX + (wm + g    ) * XS + o * DIMT + d;
            uint32_t* hi = sX + (wm + g + 8) * XS + o * DIMT + d;
            lo[0]    = __float_as_uint(ALPHA_F * c[dd][nt][0]);
            lo[DIMT] = __float_as_uint(ALPHA_F * c[dd][nt][1]);
            hi[0]    = __float_as_uint(ALPHA_F * c[dd][nt][2]);
            hi[DIMT] = __float_as_uint(ALPHA_F * c[dd][nt][3]);
        }
    }
}

__global__ void __launch_bounds__(NTHREADS, 1)
aligned_linear_tf32(const float* __restrict__ x,
                    const float* __restrict__ kern,
                    float* __restrict__ y,
                    int n_nodes)
{
    extern __shared__ uint32_t smem[];
    uint32_t* sX = smem;               // [MT][XS]  X tile -> becomes Y tile
    uint32_t* sK = smem + MT * XS;     // [MUL][KS] current irrep weights

    const int tid  = threadIdx.x;
    const int lane = tid & 31;
    const int warp = tid >> 5;
    const int g    = lane >> 2;
    const int tg   = lane & 3;
    const int wm   = (warp & 1) * 16;           // 2 warp rows (M)
    const int wn   = (warp >> 1) * WN_TILE;     // 8 warp cols (N), 16 each

    const long long node0 = (long long)blockIdx.x * MT;

    // ---- Stage X tile: coalesced float4 loads, convert to tf32 ----
    #pragma unroll
    for (int it = tid; it < MT * (ROWF / 4); it += NTHREADS) {
        int row = it / (ROWF / 4);
        int c4  = it - row * (ROWF / 4);
        long long n = node0 + row;
        float4 v = make_float4(0.f, 0.f, 0.f, 0.f);
        if (n < (long long)n_nodes)
            v = *reinterpret_cast<const float4*>(x + n * ROWF + c4 * 4);
        uint32_t* dst = sX + row * XS + c4 * 4;
        dst[0] = f2tf32(v.x);
        dst[1] = f2tf32(v.y);
        dst[2] = f2tf32(v.z);
        dst[3] = f2tf32(v.w);
    }

    process_group<0, 0, 1>(sX, sK, kern, tid, g, tg, wm, wn);
    process_group<1, 1, 3>(sX, sK, kern, tid, g, tg, wm, wn);
    process_group<2, 4, 5>(sX, sK, kern, tid, g, tg, wm, wn);

    __syncthreads();   // all writebacks visible

    // ---- Single coalesced store of the whole output tile ----
    #pragma unroll
    for (int it = tid; it < MT * (ROWF / 4); it += NTHREADS) {
        int row = it / (ROWF / 4);
        int c4  = it - row * (ROWF / 4);
        long long n = node0 + row;
        if (n < (long long)n_nodes) {
            const uint32_t* src = sX + row * XS + c4 * 4;
            float4 v;
            v.x = __uint_as_float(src[0]);
            v.y = __uint_as_float(src[1]);
            v.z = __uint_as_float(src[2]);
            v.w = __uint_as_float(src[3]);
            *reinterpret_cast<float4*>(y + n * ROWF + c4 * 4) = v;
        }
    }
}

extern "C" void kernel_launch(void* const* d_in, const int* in_sizes, int n_in,
                              void* d_out, int out_size)
{
    const float* x = (const float*)d_in[0];
    const float* k = (const float*)d_in[1];
    float* y = (float*)d_out;
    int n_nodes = in_sizes[0] / ROWF;

    size_t smem_bytes = (size_t)(MT * XS + MUL * KS) * sizeof(uint32_t);
    cudaFuncSetAttribute(aligned_linear_tf32,
                         cudaFuncAttributeMaxDynamicSharedMemorySize,
                         (int)smem_bytes);

    int grid = (n_nodes + MT - 1) / MT;
    aligned_linear_tf32<<<grid, NTHREADS, smem_bytes>>>(x, k, y, n_nodes);
}

// round 6
// speedup vs baseline: 1.6672x; 1.6672x over previous
#include <cuda_runtime.h>
#include <cstdint>

// AlignedLinear: y[n, o*9+d] = alpha * sum_i x[n, i*9+d] * K[r(d), i, o]
// r(d)=0 for d=0, 1 for d=1..3, 2 for d=4..8.
//
// R6: MT=16 tiles, 128 threads (4 warps x nt=4), 3 CTAs/SM for phase overlap.
// K pre-converted to a fragment-major tf32 global buffer by a prep kernel;
// B fragments loaded as one coalesced LDG.64 per (kk,nt), double-buffered.
// X staged in SMEM (tf32), outputs overwrite dead X columns, one coalesced
// store at the end.

#define MT        16
#define DIMT      9
#define MUL       128
#define ROWF      1152          // MUL*DIMT
#define XS        1156          // ROWF+4: stride-9 A reads bank-conflict-free
#define NTHREADS  128
#define ALPHA_F   0.08838834764831845f  // sqrt(1/128)

// kbuf[r][k8][nt][lane][j] : b_j for thread `lane` of fragment (k8, nt), irrep r
#define KB_WORDS  (3 * 16 * 16 * 64)
__device__ uint32_t g_kbuf[KB_WORDS];

static __device__ __forceinline__ uint32_t f2tf32(float f) {
    uint32_t u;
    asm("cvt.rna.tf32.f32 %0, %1;" : "=r"(u) : "f"(f));
    return u;
}

static __device__ __forceinline__ void mma_tf32(float c[4],
    uint32_t a0, uint32_t a1, uint32_t a2, uint32_t a3,
    uint32_t b0, uint32_t b1)
{
    asm volatile(
        "mma.sync.aligned.m16n8k8.row.col.f32.tf32.tf32.f32 "
        "{%0,%1,%2,%3}, {%4,%5,%6,%7}, {%8,%9}, {%0,%1,%2,%3};"
        : "+f"(c[0]), "+f"(c[1]), "+f"(c[2]), "+f"(c[3])
        : "r"(a0), "r"(a1), "r"(a2), "r"(a3), "r"(b0), "r"(b1));
}

// ---- Prep: K[r][i][o] fp32 -> fragment-major tf32 (RTN) ----
__global__ void prep_k_kernel(const float* __restrict__ kern)
{
    int idx = blockIdx.x * blockDim.x + threadIdx.x;
    if (idx >= KB_WORDS) return;
    int j    = idx & 1;
    int lane = (idx >> 1) & 31;
    int nt   = (idx >> 6) & 15;
    int k8   = (idx >> 10) & 15;
    int r    = idx >> 14;
    int k = k8 * 8 + (lane & 3) + 4 * j;   // row in K
    int o = nt * 8 + (lane >> 2);          // col in K
    g_kbuf[idx] = f2tf32(kern[(r * MUL + k) * MUL + o]);
}

// One irrep group: GEMM all DC dims over k (B from g_kbuf, double-buffered),
// then write alpha*C back into sX over the now-dead X columns o*9+d.
template<int R, int D0, int DC>
static __device__ __forceinline__ void process_group(
    uint32_t* __restrict__ sX, int g, int tg, int lane, int wn)
{
    const uint2* kb = reinterpret_cast<const uint2*>(g_kbuf)
                    + ((size_t)R * 16 * 16 + (wn >> 3)) * 32 + lane;

    float c[DC][4][4];
    #pragma unroll
    for (int dd = 0; dd < DC; ++dd)
        #pragma unroll
        for (int nt = 0; nt < 4; ++nt)
            #pragma unroll
            for (int i = 0; i < 4; ++i) c[dd][nt][i] = 0.f;

    uint2 bcur[4];
    #pragma unroll
    for (int nt = 0; nt < 4; ++nt)
        bcur[nt] = __ldg(kb + nt * 32);

    #pragma unroll 1
    for (int k8 = 0; k8 < 16; ++k8) {
        uint2 bnxt[4];
        if (k8 < 15) {
            const uint2* kbn = kb + (k8 + 1) * (16 * 32);
            #pragma unroll
            for (int nt = 0; nt < 4; ++nt)
                bnxt[nt] = __ldg(kbn + nt * 32);
        }
        const int kk = k8 * 8;
        #pragma unroll
        for (int dd = 0; dd < DC; ++dd) {
            const int d = D0 + dd;
            uint32_t a0 = sX[(g    ) * XS + (kk + tg    ) * DIMT + d];
            uint32_t a1 = sX[(g + 8) * XS + (kk + tg    ) * DIMT + d];
            uint32_t a2 = sX[(g    ) * XS + (kk + tg + 4) * DIMT + d];
            uint32_t a3 = sX[(g + 8) * XS + (kk + tg + 4) * DIMT + d];
            #pragma unroll
            for (int nt = 0; nt < 4; ++nt)
                mma_tf32(c[dd][nt], a0, a1, a2, a3, bcur[nt].x, bcur[nt].y);
        }
        #pragma unroll
        for (int nt = 0; nt < 4; ++nt) bcur[nt] = bnxt[nt];
    }

    __syncthreads();   // all warps done reading this group's X columns

    #pragma unroll
    for (int dd = 0; dd < DC; ++dd) {
        const int d = D0 + dd;
        #pragma unroll
        for (int nt = 0; nt < 4; ++nt) {
            int o = wn + nt * 8 + 2 * tg;
            uint32_t* lo = sX + (g    ) * XS + o * DIMT + d;
            uint32_t* hi = sX + (g + 8) * XS + o * DIMT + d;
            lo[0]    = __float_as_uint(ALPHA_F * c[dd][nt][0]);
            lo[DIMT] = __float_as_uint(ALPHA_F * c[dd][nt][1]);
            hi[0]    = __float_as_uint(ALPHA_F * c[dd][nt][2]);
            hi[DIMT] = __float_as_uint(ALPHA_F * c[dd][nt][3]);
        }
    }
}

__global__ void __launch_bounds__(NTHREADS, 3)
aligned_linear_tf32(const float* __restrict__ x,
                    float* __restrict__ y,
                    int n_nodes)
{
    extern __shared__ uint32_t sX[];   // [MT][XS]  X tile -> becomes Y tile

    const int tid  = threadIdx.x;
    const int lane = tid & 31;
    const int warp = tid >> 5;
    const int g    = lane >> 2;
    const int tg   = lane & 3;
    const int wn   = warp * 32;        // 4 warps x 32 output cols

    const long long node0 = (long long)blockIdx.x * MT;

    // ---- Stage X tile: coalesced float4 loads, convert to tf32 ----
    #pragma unroll
    for (int it = tid; it < MT * (ROWF / 4); it += NTHREADS) {
        int row = it / (ROWF / 4);
        int c4  = it - row * (ROWF / 4);
        long long n = node0 + row;
        float4 v = make_float4(0.f, 0.f, 0.f, 0.f);
        if (n < (long long)n_nodes)
            v = *reinterpret_cast<const float4*>(x + n * ROWF + c4 * 4);
        uint32_t* dst = sX + row * XS + c4 * 4;
        dst[0] = f2tf32(v.x);
        dst[1] = f2tf32(v.y);
        dst[2] = f2tf32(v.z);
        dst[3] = f2tf32(v.w);
    }
    __syncthreads();

    process_group<0, 0, 1>(sX, g, tg, lane, wn);
    process_group<1, 1, 3>(sX, g, tg, lane, wn);
    process_group<2, 4, 5>(sX, g, tg, lane, wn);

    __syncthreads();   // all writebacks visible

    // ---- Single coalesced store of the whole output tile ----
    #pragma unroll
    for (int it = tid; it < MT * (ROWF / 4); it += NTHREADS) {
        int row = it / (ROWF / 4);
        int c4  = it - row * (ROWF / 4);
        long long n = node0 + row;
        if (n < (long long)n_nodes) {
            const uint32_t* src = sX + row * XS + c4 * 4;
            float4 v;
            v.x = __uint_as_float(src[0]);
            v.y = __uint_as_float(src[1]);
            v.z = __uint_as_float(src[2]);
            v.w = __uint_as_float(src[3]);
            *reinterpret_cast<float4*>(y + n * ROWF + c4 * 4) = v;
        }
    }
}

extern "C" void kernel_launch(void* const* d_in, const int* in_sizes, int n_in,
                              void* d_out, int out_size)
{
    const float* x = (const float*)d_in[0];
    const float* k = (const float*)d_in[1];
    float* y = (float*)d_out;
    int n_nodes = in_sizes[0] / ROWF;

    prep_k_kernel<<<(KB_WORDS + 255) / 256, 256>>>(k);

    size_t smem_bytes = (size_t)(MT * XS) * sizeof(uint32_t);  // ~74 KB
    cudaFuncSetAttribute(aligned_linear_tf32,
                         cudaFuncAttributeMaxDynamicSharedMemorySize,
                         (int)smem_bytes);

    int grid = (n_nodes + MT - 1) / MT;
    aligned_linear_tf32<<<grid, NTHREADS, smem_bytes>>>(x, y, n_nodes);
}